// round 2
// baseline (speedup 1.0000x reference)
#include <cuda_runtime.h>

// SSIM loss, fully fused single kernel:
//   4 separable 11-tap convs (x, y, x*y, x^2+y^2), horizontal -> smem -> vertical,
//   per-pixel SSIM, block reduce, last-block finish writes scalar output.
// Tile: 32x32 outputs, halo 5 -> 42x42 region. 256 threads/block.

#define TW 32
#define TH 32
#define RW 42          // TW + 10
#define RH 42          // TH + 10
#define SXP 43         // padded row stride for input tiles (43%32=11 -> conflict-free)
#define HP  33         // padded row stride for intermediate tiles
#define NTHREADS 256
#define NPIX (16*3*512*512)
#define NBLOCKS (16*16*48)

// Gaussian(sigma=1.5) 11-tap, normalized
__device__ constexpr float Wg[11] = {
    0.00102838f, 0.00759875f, 0.03600077f, 0.10936070f, 0.21300553f,
    0.26601172f,
    0.21300553f, 0.10936070f, 0.03600077f, 0.00759875f, 0.00102838f};

__device__ double g_acc = 0.0;
__device__ unsigned g_cnt = 0u;

__global__ void __launch_bounds__(NTHREADS, 3)
ssim_main(const float* __restrict__ pred, const float* __restrict__ targ,
          float* __restrict__ out) {
    __shared__ float sx[RH][SXP];
    __shared__ float sy[RH][SXP];
    __shared__ float hh[4][RH][HP];
    __shared__ float red[8];

    const int tid = threadIdx.x;
    const int plane = blockIdx.z;
    const int gx0 = blockIdx.x * TW - 5;
    const int gy0 = blockIdx.y * TH - 5;
    const float* __restrict__ px = pred + (size_t)plane * (512 * 512);
    const float* __restrict__ py = targ + (size_t)plane * (512 * 512);

    // ---- load 42x42 halo region (zero-padded at borders) ----
    for (int i = tid; i < RH * RW; i += NTHREADS) {
        int r = i / RW;
        int c = i - r * RW;
        int gy = gy0 + r, gx = gx0 + c;
        float vx = 0.f, vy = 0.f;
        if ((unsigned)gy < 512u && (unsigned)gx < 512u) {
            int idx = gy * 512 + gx;
            vx = px[idx];
            vy = py[idx];
        }
        sx[r][c] = vx;
        sy[r][c] = vy;
    }
    __syncthreads();

    // ---- horizontal pass: 42 rows x 4 segments of 8 outputs ----
    // Liveness-ordered to keep peak registers low:
    //   a,b -> pb -> ap(conv) -> sb(reuse pb) -> as(conv) -> ax -> ay.
    for (int t = tid; t < RH * 4; t += NTHREADS) {
        const int row = t >> 2;
        const int c0 = (t & 3) * 8;
        float a[18], b[18];
#pragma unroll
        for (int k = 0; k < 18; k++) {
            a[k] = sx[row][c0 + k];
            b[k] = sy[row][c0 + k];
        }
        float acc[8], tbuf[18];

        // E[xy] horizontal
#pragma unroll
        for (int k = 0; k < 18; k++) tbuf[k] = a[k] * b[k];
#pragma unroll
        for (int j = 0; j < 8; j++) acc[j] = 0.f;
#pragma unroll
        for (int k = 0; k < 11; k++)
#pragma unroll
            for (int j = 0; j < 8; j++) acc[j] += Wg[k] * tbuf[j + k];
#pragma unroll
        for (int j = 0; j < 8; j++) hh[2][row][c0 + j] = acc[j];

        // E[x^2+y^2] horizontal (tbuf reused)
#pragma unroll
        for (int k = 0; k < 18; k++) tbuf[k] = fmaf(a[k], a[k], b[k] * b[k]);
#pragma unroll
        for (int j = 0; j < 8; j++) acc[j] = 0.f;
#pragma unroll
        for (int k = 0; k < 11; k++)
#pragma unroll
            for (int j = 0; j < 8; j++) acc[j] += Wg[k] * tbuf[j + k];
#pragma unroll
        for (int j = 0; j < 8; j++) hh[3][row][c0 + j] = acc[j];

        // mu_x horizontal (a dies after this)
#pragma unroll
        for (int j = 0; j < 8; j++) acc[j] = 0.f;
#pragma unroll
        for (int k = 0; k < 11; k++)
#pragma unroll
            for (int j = 0; j < 8; j++) acc[j] += Wg[k] * a[j + k];
#pragma unroll
        for (int j = 0; j < 8; j++) hh[0][row][c0 + j] = acc[j];

        // mu_y horizontal
#pragma unroll
        for (int j = 0; j < 8; j++) acc[j] = 0.f;
#pragma unroll
        for (int k = 0; k < 11; k++)
#pragma unroll
            for (int j = 0; j < 8; j++) acc[j] += Wg[k] * b[j + k];
#pragma unroll
        for (int j = 0; j < 8; j++) hh[1][row][c0 + j] = acc[j];
    }
    __syncthreads();

    // ---- vertical pass: thread owns column tx, rows g*4..g*4+3 ----
    const int tx = tid & 31;
    const int g = tid >> 5;
    float vac[4][4];
#pragma unroll
    for (int m = 0; m < 4; m++)
#pragma unroll
        for (int j = 0; j < 4; j++) vac[m][j] = 0.f;

#pragma unroll
    for (int m = 0; m < 4; m++) {
        float v[14];
#pragma unroll
        for (int k = 0; k < 14; k++) v[k] = hh[m][g * 4 + k][tx];
#pragma unroll
        for (int k = 0; k < 11; k++)
#pragma unroll
            for (int j = 0; j < 4; j++)
                vac[m][j] += Wg[k] * v[j + k];
    }

    // ---- SSIM + thread-local sum ----
    const float C1 = 1e-4f, C2 = 9e-4f;
    float local = 0.f;
#pragma unroll
    for (int j = 0; j < 4; j++) {
        float mx = vac[0][j], my = vac[1][j];
        float ep = vac[2][j], es = vac[3][j];
        float muxy = mx * my;
        float mu2  = fmaf(mx, mx, my * my);
        float sxy  = ep - muxy;
        float ssum = es - mu2;
        float num = (2.f * muxy + C1) * (2.f * sxy + C2);
        float den = (mu2 + C1) * (ssum + C2);
        local += __fdividef(num, den);
    }

    // ---- block reduce ----
#pragma unroll
    for (int o = 16; o > 0; o >>= 1)
        local += __shfl_down_sync(0xffffffffu, local, o);
    if (tx == 0) red[g] = local;
    __syncthreads();

    // ---- last-block finish: deterministic across graph replays ----
    if (tid == 0) {
        float s = 0.f;
#pragma unroll
        for (int i = 0; i < 8; i++) s += red[i];
        atomicAdd(&g_acc, (double)s);
        __threadfence();
        unsigned ticket = atomicAdd(&g_cnt, 1u);
        if (ticket == (unsigned)(NBLOCKS - 1)) {
            double tot = atomicAdd(&g_acc, 0.0);   // read final sum
            out[0] = 1.0f - (float)(tot * (1.0 / (double)NPIX));
            // reset for next replay (stream-ordered before next launch)
            g_acc = 0.0;
            __threadfence();
            g_cnt = 0u;
        }
    }
}

extern "C" void kernel_launch(void* const* d_in, const int* in_sizes, int n_in,
                              void* d_out, int out_size) {
    const float* pred = (const float*)d_in[0];
    const float* targ = (const float*)d_in[1];
    float* out = (float*)d_out;

    dim3 grid(512 / TW, 512 / TH, 48);
    ssim_main<<<grid, NTHREADS>>>(pred, targ, out);
}

// round 4
// speedup vs baseline: 1.0580x; 1.0580x over previous
#include <cuda_runtime.h>

// SSIM loss, fully fused single kernel, f32x2-packed separable convs.
//   m2 = (x, y) packed         -> conv gives (mu_x, mu_y)
//   p2 = (x*y, x^2+y^2) packed -> conv gives (E[xy], E[x^2+y^2])
// Horizontal (rows) -> smem -> vertical (cols) -> SSIM -> block reduce ->
// last-block finish writes scalar.
// Tile 32x32 outputs, halo 5 -> 42x42 region, 256 threads/block.

#define TW 32
#define TH 32
#define RW 42
#define RH 42
#define S2 43            // float2 row stride, input tile (odd -> conflict-free)
#define H2 33            // float2 row stride, intermediates (odd)
#define NTHREADS 256
#define NPIX (16*3*512*512)
#define NBLOCKS (16*16*48)

typedef unsigned long long u64;

// Gaussian(sigma=1.5) 11-tap, normalized; symmetric -> 6 distinct
__device__ constexpr float Wg[6] = {
    0.00102838f, 0.00759875f, 0.03600077f, 0.10936070f, 0.21300553f,
    0.26601172f};

__device__ double g_acc = 0.0;
__device__ unsigned g_cnt = 0u;

__device__ __forceinline__ u64 pk(float lo, float hi) {
    u64 r;
    asm("mov.b64 %0, {%1, %2};" : "=l"(r) : "f"(lo), "f"(hi));
    return r;
}
__device__ __forceinline__ void upk(float& lo, float& hi, u64 v) {
    asm("mov.b64 {%0, %1}, %2;" : "=f"(lo), "=f"(hi) : "l"(v));
}
__device__ __forceinline__ void pfma(u64& acc, u64 a, u64 w) {
    asm("fma.rn.f32x2 %0, %1, %2, %0;" : "+l"(acc) : "l"(a), "l"(w));
}

__global__ void __launch_bounds__(NTHREADS, 3)
ssim_main(const float* __restrict__ pred, const float* __restrict__ targ,
          float* __restrict__ out) {
    __shared__ float2 sxy[RH][S2];
    __shared__ float2 hm[RH][H2];
    __shared__ float2 hp[RH][H2];
    __shared__ float red[8];

    const int tid = threadIdx.x;
    const int plane = blockIdx.z;
    const int gx0 = blockIdx.x * TW - 5;
    const int gy0 = blockIdx.y * TH - 5;
    const float* __restrict__ px = pred + (size_t)plane * (512 * 512);
    const float* __restrict__ py = targ + (size_t)plane * (512 * 512);

    // packed symmetric weights (register-resident)
    u64 w2[6];
#pragma unroll
    for (int k = 0; k < 6; k++) w2[k] = pk(Wg[k], Wg[k]);

    // ---- load 42x42 halo region, interleaved (x,y), zero-padded ----
    for (int i = tid; i < RH * RW; i += NTHREADS) {
        int r = i / RW;
        int c = i - r * RW;
        int gy = gy0 + r, gx = gx0 + c;
        float vx = 0.f, vy = 0.f;
        if ((unsigned)gy < 512u && (unsigned)gx < 512u) {
            int idx = gy * 512 + gx;
            vx = px[idx];
            vy = py[idx];
        }
        sxy[r][c] = make_float2(vx, vy);
    }
    __syncthreads();

    // ---- horizontal pass: 42 rows x 4 segments of 8 outputs ----
    if (tid < RH * 4) {
        const int row = tid % RH;          // warp lanes -> consecutive rows
        const int c0 = (tid / RH) * 8;
        const u64* __restrict__ srow = (const u64*)&sxy[row][0];
        u64* __restrict__ hmrow = (u64*)&hm[row][0];
        u64* __restrict__ hprow = (u64*)&hp[row][0];

        u64 m[18];
#pragma unroll
        for (int i = 0; i < 18; i++) m[i] = srow[c0 + i];

        // conv (mu_x, mu_y)
        {
            u64 acc[8];
#pragma unroll
            for (int j = 0; j < 8; j++) acc[j] = 0ull;
#pragma unroll
            for (int k = 0; k < 11; k++) {
                const u64 wk = w2[k < 6 ? k : 10 - k];
#pragma unroll
                for (int j = 0; j < 8; j++) pfma(acc[j], m[j + k], wk);
            }
#pragma unroll
            for (int j = 0; j < 8; j++) hmrow[c0 + j] = acc[j];
        }

        // build p2 = (x*y, x^2+y^2) in place
#pragma unroll
        for (int i = 0; i < 18; i++) {
            float a, b;
            upk(a, b, m[i]);
            m[i] = pk(a * b, fmaf(a, a, b * b));
        }

        // conv (E[xy], E[x^2+y^2])
        {
            u64 acc[8];
#pragma unroll
            for (int j = 0; j < 8; j++) acc[j] = 0ull;
#pragma unroll
            for (int k = 0; k < 11; k++) {
                const u64 wk = w2[k < 6 ? k : 10 - k];
#pragma unroll
                for (int j = 0; j < 8; j++) pfma(acc[j], m[j + k], wk);
            }
#pragma unroll
            for (int j = 0; j < 8; j++) hprow[c0 + j] = acc[j];
        }
    }
    __syncthreads();

    // ---- vertical pass: thread owns column tx, rows g*4..g*4+3 ----
    const int tx = tid & 31;
    const int g = tid >> 5;

    u64 am[4], ap[4];
    {
        u64 v[14];
#pragma unroll
        for (int k = 0; k < 14; k++) v[k] = ((const u64*)&hm[g * 4 + k][0])[tx];
#pragma unroll
        for (int j = 0; j < 4; j++) am[j] = 0ull;
#pragma unroll
        for (int k = 0; k < 11; k++) {
            const u64 wk = w2[k < 6 ? k : 10 - k];
#pragma unroll
            for (int j = 0; j < 4; j++) pfma(am[j], v[j + k], wk);
        }
#pragma unroll
        for (int k = 0; k < 14; k++) v[k] = ((const u64*)&hp[g * 4 + k][0])[tx];
#pragma unroll
        for (int j = 0; j < 4; j++) ap[j] = 0ull;
#pragma unroll
        for (int k = 0; k < 11; k++) {
            const u64 wk = w2[k < 6 ? k : 10 - k];
#pragma unroll
            for (int j = 0; j < 4; j++) pfma(ap[j], v[j + k], wk);
        }
    }

    // ---- SSIM + thread-local sum ----
    const float C1 = 1e-4f, C2 = 9e-4f;
    float local = 0.f;
#pragma unroll
    for (int j = 0; j < 4; j++) {
        float mx, my, exy, es;
        upk(mx, my, am[j]);
        upk(exy, es, ap[j]);
        float muxy = mx * my;
        float mu2 = fmaf(mx, mx, my * my);
        float sxyv = exy - muxy;
        float ssum = es - mu2;
        float num = (2.f * muxy + C1) * (2.f * sxyv + C2);
        float den = (mu2 + C1) * (ssum + C2);
        local += __fdividef(num, den);
    }

    // ---- block reduce ----
#pragma unroll
    for (int o = 16; o > 0; o >>= 1)
        local += __shfl_down_sync(0xffffffffu, local, o);
    if (tx == 0) red[g] = local;
    __syncthreads();

    // ---- last-block finish ----
    if (tid == 0) {
        float s = 0.f;
#pragma unroll
        for (int i = 0; i < 8; i++) s += red[i];
        atomicAdd(&g_acc, (double)s);
        __threadfence();
        unsigned ticket = atomicAdd(&g_cnt, 1u);
        if (ticket == (unsigned)(NBLOCKS - 1)) {
            double tot = atomicAdd(&g_acc, 0.0);
            out[0] = 1.0f - (float)(tot * (1.0 / (double)NPIX));
            g_acc = 0.0;
            __threadfence();
            g_cnt = 0u;
        }
    }
}

extern "C" void kernel_launch(void* const* d_in, const int* in_sizes, int n_in,
                              void* d_out, int out_size) {
    const float* pred = (const float*)d_in[0];
    const float* targ = (const float*)d_in[1];
    float* out = (float*)d_out;

    dim3 grid(512 / TW, 512 / TH, 48);
    ssim_main<<<grid, NTHREADS>>>(pred, targ, out);
}

// round 5
// speedup vs baseline: 1.6205x; 1.5316x over previous
#include <cuda_runtime.h>

// SSIM loss — vertical-first fused design.
// Phase 1: each thread owns one column, slides an 11-row ring window down it,
//   loading pred/targ straight from global (coalesced), producing packed
//   v-conv results (mu_x,mu_y) and (E[xy],E[x^2+y^2]) -> one float4 per (row,col) in smem.
// Phase 2: horizontal 11-tap conv along rows from smem, SSIM, block reduce,
//   last-block finish writes the scalar.
// Tile: 22 wide x 64 tall outputs; region 32 wide. f32x2 packed FMAs throughout.

#define TW 22
#define RWID 32
#define TH 64
#define CHUNK 8          // rows per thread in phase 1 (8 groups * 8 = 64)
#define SP 33            // float4 row stride (odd -> conflict-free)
#define NTHREADS 256
#define GRIDX 24         // ceil(512/22), last block ragged (predicated)
#define NPIX (16*3*512*512)
#define NBLOCKS (GRIDX*8*48)

typedef unsigned long long u64;

// Gaussian(sigma=1.5) 11-tap, normalized; symmetric -> 6 distinct
__device__ constexpr float Wg[6] = {
    0.00102838f, 0.00759875f, 0.03600077f, 0.10936070f, 0.21300553f,
    0.26601172f};

__device__ double g_acc = 0.0;
__device__ unsigned g_cnt = 0u;

__device__ __forceinline__ u64 pk(float lo, float hi) {
    u64 r;
    asm("mov.b64 %0, {%1, %2};" : "=l"(r) : "f"(lo), "f"(hi));
    return r;
}
__device__ __forceinline__ void upk(float& lo, float& hi, u64 v) {
    asm("mov.b64 {%0, %1}, %2;" : "=f"(lo), "=f"(hi) : "l"(v));
}
__device__ __forceinline__ void pfma(u64& acc, u64 a, u64 w) {
    asm("fma.rn.f32x2 %0, %1, %2, %0;" : "+l"(acc) : "l"(a), "l"(w));
}

__global__ void __launch_bounds__(NTHREADS)
ssim_main(const float* __restrict__ pred, const float* __restrict__ targ,
          float* __restrict__ out) {
    __shared__ float4 vmp[TH][SP];     // (m.lo, m.hi, p.lo, p.hi) per (row,col)
    __shared__ float red[8];

    const int tid = threadIdx.x;
    const int plane = blockIdx.z;
    const float* __restrict__ px = pred + (size_t)plane * (512 * 512);
    const float* __restrict__ py = targ + (size_t)plane * (512 * 512);

    u64 w2[6];
#pragma unroll
    for (int k = 0; k < 6; k++) w2[k] = pk(Wg[k], Wg[k]);

    // ================= Phase 1: vertical conv from global =================
    {
        const int col = tid & 31;            // region column 0..31
        const int g = tid >> 5;              // row group 0..7
        const int gx = blockIdx.x * TW - 5 + col;
        const bool colok = (unsigned)gx < 512u;
        const int gybase = blockIdx.y * TH + g * CHUNK - 5;

        u64 wm[11], wp[11];
#pragma unroll
        for (int i = 0; i < 10; i++) {
            int gy = gybase + i;
            bool v = colok && ((unsigned)gy < 512u);
            int idx = gy * 512 + gx;
            float a = v ? px[idx] : 0.f;
            float b = v ? py[idx] : 0.f;
            wm[i] = pk(a, b);
            wp[i] = pk(a * b, fmaf(a, a, b * b));
        }
#pragma unroll
        for (int j = 0; j < CHUNK; j++) {
            {   // load row j+10 into ring slot (j+10)%11
                int i = j + 10;
                int gy = gybase + i;
                bool v = colok && ((unsigned)gy < 512u);
                int idx = gy * 512 + gx;
                float a = v ? px[idx] : 0.f;
                float b = v ? py[idx] : 0.f;
                wm[i % 11] = pk(a, b);
                wp[i % 11] = pk(a * b, fmaf(a, a, b * b));
            }
            u64 am = 0ull, ap = 0ull;
#pragma unroll
            for (int t = 0; t < 11; t++) {
                const u64 wk = w2[t < 6 ? t : 10 - t];
                pfma(am, wm[(j + t) % 11], wk);
                pfma(ap, wp[(j + t) % 11], wk);
            }
            float4 o;
            upk(o.x, o.y, am);
            upk(o.z, o.w, ap);
            vmp[g * CHUNK + j][col] = o;
        }
    }
    __syncthreads();

    // ================= Phase 2: horizontal conv + SSIM =================
    float local = 0.f;
    {
        const int row = tid & 63;            // 0..63
        const int q = tid >> 6;              // 0..3
        const int lbase = (q == 3) ? 16 : q * 6;   // load-col base; outputs at region cols lbase+5+j

        u64 am[6], ap[6];
#pragma unroll
        for (int j = 0; j < 6; j++) { am[j] = 0ull; ap[j] = 0ull; }

#pragma unroll
        for (int k = 0; k < 16; k++) {
            float4 v = vmp[row][lbase + k];
            u64 vm = pk(v.x, v.y);
            u64 vp = pk(v.z, v.w);
#pragma unroll
            for (int j = 0; j < 6; j++) {
                const int t = k - j;
                if (t >= 0 && t <= 10) {
                    const u64 wk = w2[t < 6 ? t : 10 - t];
                    pfma(am[j], vm, wk);
                    pfma(ap[j], vp, wk);
                }
            }
        }

        const float C1 = 1e-4f, C2 = 9e-4f;
        const int xbase = blockIdx.x * TW + lbase;
#pragma unroll
        for (int j = 0; j < 6; j++) {
            float mx, my, exy, es;
            upk(mx, my, am[j]);
            upk(exy, es, ap[j]);
            float muxy = mx * my;
            float mu2 = fmaf(mx, mx, my * my);
            float sxyv = exy - muxy;
            float ssum = es - mu2;
            float num = (2.f * muxy + C1) * (2.f * sxyv + C2);
            float den = (mu2 + C1) * (ssum + C2);
            bool use = (q != 3 || j >= 2) && (xbase + j < 512);
            if (use) local += __fdividef(num, den);
        }
    }

    // ---- block reduce ----
#pragma unroll
    for (int o = 16; o > 0; o >>= 1)
        local += __shfl_down_sync(0xffffffffu, local, o);
    if ((tid & 31) == 0) red[tid >> 5] = local;
    __syncthreads();

    // ---- last-block finish ----
    if (tid == 0) {
        float s = 0.f;
#pragma unroll
        for (int i = 0; i < 8; i++) s += red[i];
        atomicAdd(&g_acc, (double)s);
        __threadfence();
        unsigned ticket = atomicAdd(&g_cnt, 1u);
        if (ticket == (unsigned)(NBLOCKS - 1)) {
            double tot = atomicAdd(&g_acc, 0.0);
            out[0] = 1.0f - (float)(tot * (1.0 / (double)NPIX));
            g_acc = 0.0;
            __threadfence();
            g_cnt = 0u;
        }
    }
}

extern "C" void kernel_launch(void* const* d_in, const int* in_sizes, int n_in,
                              void* d_out, int out_size) {
    const float* pred = (const float*)d_in[0];
    const float* targ = (const float*)d_in[1];
    float* out = (float*)d_out;

    dim3 grid(GRIDX, 512 / TH, 48);
    ssim_main<<<grid, NTHREADS>>>(pred, targ, out);
}

// round 6
// speedup vs baseline: 1.8230x; 1.1249x over previous
#include <cuda_runtime.h>

// SSIM loss — vertical-first fused design, scatter-accumulator phase 1.
// Phase 1: each thread owns one column and 8 output rows; streams 18 input
//   rows from global (coalesced), scattering each into the <=8 v-conv
//   accumulators it affects (packed f32x2: (mu_x,mu_y) and (E[xy],E[x2+y2])).
//   One float4 per (row,col) into smem.
// Phase 2: horizontal 11-tap conv along rows from smem, SSIM, block reduce,
//   last-block finish writes the scalar.
// Tile: 22 wide x 64 tall outputs; region 32 wide. 256 threads/block.

#define TW 22
#define TH 64
#define CHUNK 8
#define SP 33            // float4 row stride (odd -> conflict-free)
#define NTHREADS 256
#define GRIDX 24         // ceil(512/22), last block ragged (predicated)
#define NPIX (16*3*512*512)
#define NBLOCKS (GRIDX*8*48)

typedef unsigned long long u64;

// Gaussian(sigma=1.5) 11-tap, normalized; symmetric -> 6 distinct
__device__ constexpr float Wg[6] = {
    0.00102838f, 0.00759875f, 0.03600077f, 0.10936070f, 0.21300553f,
    0.26601172f};

__device__ double g_acc = 0.0;
__device__ unsigned g_cnt = 0u;

__device__ __forceinline__ u64 pk(float lo, float hi) {
    u64 r;
    asm("mov.b64 %0, {%1, %2};" : "=l"(r) : "f"(lo), "f"(hi));
    return r;
}
__device__ __forceinline__ void upk(float& lo, float& hi, u64 v) {
    asm("mov.b64 {%0, %1}, %2;" : "=f"(lo), "=f"(hi) : "l"(v));
}
__device__ __forceinline__ void pfma(u64& acc, u64 a, u64 w) {
    asm("fma.rn.f32x2 %0, %1, %2, %0;" : "+l"(acc) : "l"(a), "l"(w));
}

__global__ void __launch_bounds__(NTHREADS, 4)
ssim_main(const float* __restrict__ pred, const float* __restrict__ targ,
          float* __restrict__ out) {
    __shared__ float4 vmp[TH][SP];     // (m.lo, m.hi, p.lo, p.hi) per (row,col)
    __shared__ float red[8];

    const int tid = threadIdx.x;
    const int plane = blockIdx.z;
    const float* __restrict__ px = pred + (size_t)plane * (512 * 512);
    const float* __restrict__ py = targ + (size_t)plane * (512 * 512);

    u64 w2[6];
#pragma unroll
    for (int k = 0; k < 6; k++) w2[k] = pk(Wg[k], Wg[k]);

    // ============ Phase 1: vertical conv from global, scatter form ============
    {
        const int col = tid & 31;            // region column 0..31
        const int g = tid >> 5;              // row group 0..7
        const int gx = blockIdx.x * TW - 5 + col;
        const bool colok = (unsigned)gx < 512u;
        const int gybase = blockIdx.y * TH + g * CHUNK - 5;

        u64 am[CHUNK], ap[CHUNK];
#pragma unroll
        for (int j = 0; j < CHUNK; j++) { am[j] = 0ull; ap[j] = 0ull; }

#pragma unroll
        for (int i = 0; i < CHUNK + 10; i++) {
            const int gy = gybase + i;
            const bool v = colok && ((unsigned)gy < 512u);
            const int idx = gy * 512 + gx;
            const float a = v ? px[idx] : 0.f;
            const float b = v ? py[idx] : 0.f;
            const u64 m = pk(a, b);
            const u64 p = pk(a * b, fmaf(a, a, b * b));
#pragma unroll
            for (int j = 0; j < CHUNK; j++) {
                const int t = i - j;              // tap index for output j
                if (t >= 0 && t <= 10) {
                    const u64 wk = w2[t < 6 ? t : 10 - t];
                    pfma(am[j], m, wk);
                    pfma(ap[j], p, wk);
                }
            }
        }
#pragma unroll
        for (int j = 0; j < CHUNK; j++) {
            float4 o;
            upk(o.x, o.y, am[j]);
            upk(o.z, o.w, ap[j]);
            vmp[g * CHUNK + j][col] = o;
        }
    }
    __syncthreads();

    // ============ Phase 2: horizontal conv + SSIM ============
    float local = 0.f;
    {
        const int row = tid & 63;            // 0..63
        const int q = tid >> 6;              // 0..3
        const int lbase = (q == 3) ? 16 : q * 6;   // outputs at region cols lbase+5+j

        u64 am[6], ap[6];
#pragma unroll
        for (int j = 0; j < 6; j++) { am[j] = 0ull; ap[j] = 0ull; }

#pragma unroll
        for (int k = 0; k < 16; k++) {
            float4 v = vmp[row][lbase + k];
            u64 vm = pk(v.x, v.y);
            u64 vp = pk(v.z, v.w);
#pragma unroll
            for (int j = 0; j < 6; j++) {
                const int t = k - j;
                if (t >= 0 && t <= 10) {
                    const u64 wk = w2[t < 6 ? t : 10 - t];
                    pfma(am[j], vm, wk);
                    pfma(ap[j], vp, wk);
                }
            }
        }

        const float C1 = 1e-4f, C2 = 9e-4f;
        const int xbase = blockIdx.x * TW + lbase;
#pragma unroll
        for (int j = 0; j < 6; j++) {
            float mx, my, exy, es;
            upk(mx, my, am[j]);
            upk(exy, es, ap[j]);
            float muxy = mx * my;
            float mu2 = fmaf(mx, mx, my * my);
            float sxyv = exy - muxy;
            float ssum = es - mu2;
            float num = (2.f * muxy + C1) * (2.f * sxyv + C2);
            float den = (mu2 + C1) * (ssum + C2);
            bool use = (q != 3 || j >= 2) && (xbase + j < 512);
            if (use) local += __fdividef(num, den);
        }
    }

    // ---- block reduce ----
#pragma unroll
    for (int o = 16; o > 0; o >>= 1)
        local += __shfl_down_sync(0xffffffffu, local, o);
    if ((tid & 31) == 0) red[tid >> 5] = local;
    __syncthreads();

    // ---- last-block finish ----
    if (tid == 0) {
        float s = 0.f;
#pragma unroll
        for (int i = 0; i < 8; i++) s += red[i];
        atomicAdd(&g_acc, (double)s);
        __threadfence();
        unsigned ticket = atomicAdd(&g_cnt, 1u);
        if (ticket == (unsigned)(NBLOCKS - 1)) {
            double tot = atomicAdd(&g_acc, 0.0);
            out[0] = 1.0f - (float)(tot * (1.0 / (double)NPIX));
            g_acc = 0.0;
            __threadfence();
            g_cnt = 0u;
        }
    }
}

extern "C" void kernel_launch(void* const* d_in, const int* in_sizes, int n_in,
                              void* d_out, int out_size) {
    const float* pred = (const float*)d_in[0];
    const float* targ = (const float*)d_in[1];
    float* out = (float*)d_out;

    dim3 grid(GRIDX, 512 / TH, 48);
    ssim_main<<<grid, NTHREADS>>>(pred, targ, out);
}

// round 7
// speedup vs baseline: 2.0226x; 1.1095x over previous
#include <cuda_runtime.h>

// SSIM loss — vertical-first fused design, wide tile (region 64 -> 54 outputs).
// Phase 1: 64 cols x 4 row-groups; each thread streams 18 input rows from
//   global (coalesced), scatter-accumulating 8 v-conv outputs
//   (packed f32x2: (mu_x,mu_y), (E[xy],E[x2+y2])) -> float4 per (row,col) smem.
// Phase 2: 32 rows x 8 col-groups of 7 outputs; horizontal 11-tap conv from
//   smem, SSIM, block reduce, last-block finish writes scalar.
// Tile: 54 wide x 32 tall outputs; region 64 wide x 42 tall. 256 threads.

#define TW 54
#define RW2 64           // region width = TW + 10
#define TH 32
#define CHUNK 8
#define SP 65            // float4 row stride (odd; stride%32=4 words -> conflict-free LDS.128)
#define NTHREADS 256
#define GRIDX 10         // ceil(512/54), last block ragged (predicated)
#define NPIX (16*3*512*512)
#define NBLOCKS (GRIDX*16*48)

typedef unsigned long long u64;

// Gaussian(sigma=1.5) 11-tap, normalized; symmetric -> 6 distinct
__device__ constexpr float Wg[6] = {
    0.00102838f, 0.00759875f, 0.03600077f, 0.10936070f, 0.21300553f,
    0.26601172f};

__device__ double g_acc = 0.0;
__device__ unsigned g_cnt = 0u;

__device__ __forceinline__ u64 pk(float lo, float hi) {
    u64 r;
    asm("mov.b64 %0, {%1, %2};" : "=l"(r) : "f"(lo), "f"(hi));
    return r;
}
__device__ __forceinline__ void upk(float& lo, float& hi, u64 v) {
    asm("mov.b64 {%0, %1}, %2;" : "=f"(lo), "=f"(hi) : "l"(v));
}
__device__ __forceinline__ void pfma(u64& acc, u64 a, u64 w) {
    asm("fma.rn.f32x2 %0, %1, %2, %0;" : "+l"(acc) : "l"(a), "l"(w));
}

__global__ void __launch_bounds__(NTHREADS, 4)
ssim_main(const float* __restrict__ pred, const float* __restrict__ targ,
          float* __restrict__ out) {
    __shared__ float4 vmp[TH][SP];     // (m.lo, m.hi, p.lo, p.hi) per (row,col)
    __shared__ float red[8];

    const int tid = threadIdx.x;
    const int plane = blockIdx.z;
    const float* __restrict__ px = pred + (size_t)plane * (512 * 512);
    const float* __restrict__ py = targ + (size_t)plane * (512 * 512);

    u64 w2[6];
#pragma unroll
    for (int k = 0; k < 6; k++) w2[k] = pk(Wg[k], Wg[k]);

    // ============ Phase 1: vertical conv from global, scatter form ============
    {
        const int col = tid & 63;            // region column 0..63
        const int g = tid >> 6;              // row group 0..3
        const int gx = blockIdx.x * TW - 5 + col;
        const bool colok = (unsigned)gx < 512u;
        const int gybase = blockIdx.y * TH + g * CHUNK - 5;

        u64 am[CHUNK], ap[CHUNK];
#pragma unroll
        for (int j = 0; j < CHUNK; j++) { am[j] = 0ull; ap[j] = 0ull; }

#pragma unroll
        for (int i = 0; i < CHUNK + 10; i++) {
            const int gy = gybase + i;
            const bool v = colok && ((unsigned)gy < 512u);
            const int idx = gy * 512 + gx;
            const float a = v ? px[idx] : 0.f;
            const float b = v ? py[idx] : 0.f;
            const u64 m = pk(a, b);
            const u64 p = pk(a * b, fmaf(a, a, b * b));
#pragma unroll
            for (int j = 0; j < CHUNK; j++) {
                const int t = i - j;              // tap index for output j
                if (t >= 0 && t <= 10) {
                    const u64 wk = w2[t < 6 ? t : 10 - t];
                    pfma(am[j], m, wk);
                    pfma(ap[j], p, wk);
                }
            }
        }
#pragma unroll
        for (int j = 0; j < CHUNK; j++) {
            float4 o;
            upk(o.x, o.y, am[j]);
            upk(o.z, o.w, ap[j]);
            vmp[g * CHUNK + j][col] = o;
        }
    }
    __syncthreads();

    // ============ Phase 2: horizontal conv + SSIM ============
    float local = 0.f;
    {
        const int row = tid & 31;            // 0..31
        const int tq = tid >> 5;             // 0..7, each does 7 outputs
        const int lbase = tq * 7;            // outputs at region cols lbase+j

        u64 am[7], ap[7];
#pragma unroll
        for (int j = 0; j < 7; j++) { am[j] = 0ull; ap[j] = 0ull; }

#pragma unroll
        for (int k = 0; k < 17; k++) {
            const int c = lbase + k;
            float4 v;
            if (c < RW2) v = vmp[row][c];
            else v = make_float4(0.f, 0.f, 0.f, 0.f);
            u64 vm = pk(v.x, v.y);
            u64 vp = pk(v.z, v.w);
#pragma unroll
            for (int j = 0; j < 7; j++) {
                const int t = k - j;
                if (t >= 0 && t <= 10) {
                    const u64 wk = w2[t < 6 ? t : 10 - t];
                    pfma(am[j], vm, wk);
                    pfma(ap[j], vp, wk);
                }
            }
        }

        const float C1 = 1e-4f, C2 = 9e-4f;
        const int xbase = blockIdx.x * TW + lbase;
#pragma unroll
        for (int j = 0; j < 7; j++) {
            float mx, my, exy, es;
            upk(mx, my, am[j]);
            upk(exy, es, ap[j]);
            float muxy = mx * my;
            float mu2 = fmaf(mx, mx, my * my);
            float sxyv = exy - muxy;
            float ssum = es - mu2;
            float num = (2.f * muxy + C1) * (2.f * sxyv + C2);
            float den = (mu2 + C1) * (ssum + C2);
            bool use = (lbase + j < TW) && (xbase + j < 512);
            if (use) local += __fdividef(num, den);
        }
    }

    // ---- block reduce ----
#pragma unroll
    for (int o = 16; o > 0; o >>= 1)
        local += __shfl_down_sync(0xffffffffu, local, o);
    if ((tid & 31) == 0) red[tid >> 5] = local;
    __syncthreads();

    // ---- last-block finish ----
    if (tid == 0) {
        float s = 0.f;
#pragma unroll
        for (int i = 0; i < 8; i++) s += red[i];
        atomicAdd(&g_acc, (double)s);
        __threadfence();
        unsigned ticket = atomicAdd(&g_cnt, 1u);
        if (ticket == (unsigned)(NBLOCKS - 1)) {
            double tot = atomicAdd(&g_acc, 0.0);
            out[0] = 1.0f - (float)(tot * (1.0 / (double)NPIX));
            g_acc = 0.0;
            __threadfence();
            g_cnt = 0u;
        }
    }
}

extern "C" void kernel_launch(void* const* d_in, const int* in_sizes, int n_in,
                              void* d_out, int out_size) {
    const float* pred = (const float*)d_in[0];
    const float* targ = (const float*)d_in[1];
    float* out = (float*)d_out;

    dim3 grid(GRIDX, 512 / TH, 48);
    ssim_main<<<grid, NTHREADS>>>(pred, targ, out);
}